// round 11
// baseline (speedup 1.0000x reference)
#include <cuda_runtime.h>
#include <math.h>
#include <stdint.h>

#define NN  10000
#define NE  160000
#define TT  12
#define FIN 32
#define HH  64

typedef unsigned long long ull;

// ---------- packed f32x2 helpers ----------
__device__ __forceinline__ ull ffma2(ull a, ull b, ull c){
    ull d; asm("fma.rn.f32x2 %0, %1, %2, %3;" : "=l"(d) : "l"(a), "l"(b), "l"(c)); return d;
}
__device__ __forceinline__ ull pack2(float lo, float hi){
    ull r; asm("mov.b64 %0, {%1, %2};" : "=l"(r) : "f"(lo), "f"(hi)); return r;
}
__device__ __forceinline__ void unpack2(ull v, float& lo, float& hi){
    asm("mov.b64 {%0, %1}, %2;" : "=f"(lo), "=f"(hi) : "l"(v));
}
__device__ __forceinline__ float tanha(float x){
    float y; asm("tanh.approx.f32 %0, %1;" : "=f"(y) : "f"(x)); return y;
}
__device__ __forceinline__ float fsig(float x){ return 0.5f * tanha(0.5f * x) + 0.5f; }

// ---------- tf32 mma helpers ----------
__device__ __forceinline__ uint32_t tf32cvt(float x){
    uint32_t r; asm("cvt.rna.tf32.f32 %0, %1;" : "=r"(r) : "f"(x)); return r;
}
__device__ __forceinline__ void mma_tf32(float* d, const uint32_t* a, const uint32_t* b){
    asm volatile("mma.sync.aligned.m16n8k8.row.col.f32.tf32.tf32.f32 "
        "{%0,%1,%2,%3}, {%4,%5,%6,%7}, {%8,%9}, {%0,%1,%2,%3};"
        : "+f"(d[0]), "+f"(d[1]), "+f"(d[2]), "+f"(d[3])
        : "r"(a[0]), "r"(a[1]), "r"(a[2]), "r"(a[3]), "r"(b[0]), "r"(b[1]));
}

__device__ int   g_is64;
__device__ int   g_cnt[NN];
__device__ int   g_off[NN];
__device__ int   g_cur[NN];
__device__ int   g_src[NE];
__device__ int   g_bsum[80];
__device__ float g_dis[NN];
__device__ float g_aggx[NN * TT * FIN];
__device__ float g_h0  [NN * TT * HH];
__device__ float g_agg1[NN * TT * HH];
__device__ float g_hs0 [NN * TT * HH];
__device__ float g_pre [NN * TT * 256];     // float layout: [row][hcol*4+gate], gates i,f,g,o

// ---------- CSR build ----------
__global__ void k_init(const int* __restrict__ w){
    int i = blockIdx.x * blockDim.x + threadIdx.x;
    if (i < NN) g_cnt[i] = 0;
    if (blockIdx.x == 0 && threadIdx.x == 0){
        int any = 0;
        #pragma unroll
        for (int j = 1; j < 129; j += 2) any |= w[j];
        g_is64 = (any == 0) ? 1 : 0;
    }
}

__global__ void k_count(const void* __restrict__ ei){
    int e = blockIdx.x * blockDim.x + threadIdx.x;
    if (e >= NE) return;
    int c = g_is64 ? (int)((const long long*)ei)[NE + e]
                   : ((const int*)ei)[NE + e];
    atomicAdd(&g_cnt[c], 1);
}

__global__ void k_scan1(){
    int b = blockIdx.x, t = threadIdx.x;
    int i = b * 128 + t;
    int v = (i < NN) ? g_cnt[i] : 0;
    int lane = t & 31, w = t >> 5;
    int s = v;
    #pragma unroll
    for (int d = 16; d > 0; d >>= 1) s += __shfl_down_sync(0xffffffffu, s, d);
    __shared__ int ws[4];
    if (lane == 0) ws[w] = s;
    __syncthreads();
    if (t == 0) g_bsum[b] = ws[0] + ws[1] + ws[2] + ws[3];
}

__global__ void k_scan3(){
    int b = blockIdx.x, t = threadIdx.x;
    __shared__ int sbase;
    __shared__ int ws[4];
    if (t < 32){
        int s = 0;
        for (int i = t; i < b; i += 32) s += g_bsum[i];
        #pragma unroll
        for (int d = 16; d > 0; d >>= 1) s += __shfl_down_sync(0xffffffffu, s, d);
        if (t == 0) sbase = s;
    }
    int i = b * 128 + t;
    int v = (i < NN) ? g_cnt[i] : 0;
    int lane = t & 31, w = t >> 5;
    int incl = v;
    #pragma unroll
    for (int d = 1; d < 32; d <<= 1){
        int o = __shfl_up_sync(0xffffffffu, incl, d);
        if (lane >= d) incl += o;
    }
    if (lane == 31) ws[w] = incl;
    __syncthreads();
    int base = sbase;
    for (int k = 0; k < w; ++k) base += ws[k];
    if (i < NN){
        g_off[i] = base + incl - v;
        g_cur[i] = 0;
        g_dis[i] = rsqrtf((float)(v + 1));
    }
}

__global__ void k_fill(const void* __restrict__ ei){
    int e = blockIdx.x * blockDim.x + threadIdx.x;
    if (e >= NE) return;
    int r, c;
    if (g_is64){
        r = (int)((const long long*)ei)[e];
        c = (int)((const long long*)ei)[NE + e];
    } else {
        r = ((const int*)ei)[e];
        c = ((const int*)ei)[NE + e];
    }
    int p = atomicAdd(&g_cur[c], 1);
    g_src[g_off[c] + p] = r;
}

// ---------- aggregations ----------
__global__ void k_agg_x(const float* __restrict__ x){
    int c   = blockIdx.x;
    int off = g_off[c], len = g_cnt[c];
    float dc = g_dis[c];
    int t = threadIdx.x;
    int p0 = t, p1 = t + 128, p2 = t + 256;
    int b0 = (p0 >> 5) * (NN * FIN) + (p0 & 31);
    int b1 = (p1 >> 5) * (NN * FIN) + (p1 & 31);
    int b2 = (p2 >> 5) * (NN * FIN) + (p2 & 31);
    int cb = c * FIN;
    float a0 = dc * x[b0 + cb];
    float a1 = dc * x[b1 + cb];
    float a2 = dc * x[b2 + cb];
    for (int e = 0; e < len; ++e){
        int r = g_src[off + e];
        float dr = g_dis[r];
        int rb = r * FIN;
        a0 += dr * x[b0 + rb];
        a1 += dr * x[b1 + rb];
        a2 += dr * x[b2 + rb];
    }
    g_aggx[c * 384 + p0] = dc * a0;
    g_aggx[c * 384 + p1] = dc * a1;
    g_aggx[c * 384 + p2] = dc * a2;
}

__global__ void k_agg_h(){
    int c   = blockIdx.x;
    int off = g_off[c], len = g_cnt[c];
    float dc = g_dis[c];
    int t = threadIdx.x;
    int cb = c * 768;
    float a0 = dc * g_h0[cb + t];
    float a1 = dc * g_h0[cb + t + 256];
    float a2 = dc * g_h0[cb + t + 512];
    for (int e = 0; e < len; ++e){
        int r = g_src[off + e];
        float dr = g_dis[r];
        int rb = r * 768;
        a0 += dr * g_h0[rb + t];
        a1 += dr * g_h0[rb + t + 256];
        a2 += dr * g_h0[rb + t + 512];
    }
    g_agg1[cb + t]       = dc * a0;
    g_agg1[cb + t + 256] = dc * a1;
    g_agg1[cb + t + 512] = dc * a2;
}

// ---------- GCN layer 0 GEMM (FFMA2): g_h0 = relu(g_aggx @ W + b) ----------
__global__ __launch_bounds__(256)
void k_gcn_gemm0(const float* __restrict__ W, const float* __restrict__ bvec){
    __shared__ __align__(16) float A_s[32 * 98];
    __shared__ float W_s[32 * 64];
    int t  = threadIdx.x;
    int nb = blockIdx.x * 96;

    for (int idx = t; idx < 32 * 64; idx += 256) W_s[idx] = W[idx];
    for (int idx = t; idx < 96 * 32; idx += 256){
        int n = idx >> 5, k = idx & 31;
        A_s[k * 98 + n] = g_aggx[(nb + n) * 32 + k];
    }
    __syncthreads();

    int jj = t & 31, pg = t >> 5;
    ull acc[6][2];
    #pragma unroll
    for (int p = 0; p < 6; ++p){ acc[p][0] = 0ull; acc[p][1] = 0ull; }

    #pragma unroll 8
    for (int k = 0; k < 32; ++k){
        float w0 = W_s[k * 64 + jj], w1 = W_s[k * 64 + jj + 32];
        ull W0 = pack2(w0, w0), W1 = pack2(w1, w1);
        const float* Ar = &A_s[k * 98 + pg * 12];
        #pragma unroll
        for (int p = 0; p < 6; ++p){
            ull a = *(const ull*)(Ar + 2 * p);
            acc[p][0] = ffma2(a, W0, acc[p][0]);
            acc[p][1] = ffma2(a, W1, acc[p][1]);
        }
    }
    float b0 = bvec[jj], b1 = bvec[jj + 32];
    #pragma unroll
    for (int p = 0; p < 6; ++p){
        float v0l, v0h, v1l, v1h;
        unpack2(acc[p][0], v0l, v0h);
        unpack2(acc[p][1], v1l, v1h);
        int row = nb + pg * 12 + 2 * p;
        g_h0[row * 64 + jj]            = fmaxf(v0l + b0, 0.f);
        g_h0[row * 64 + jj + 32]       = fmaxf(v1l + b1, 0.f);
        g_h0[(row + 1) * 64 + jj]      = fmaxf(v0h + b0, 0.f);
        g_h0[(row + 1) * 64 + jj + 32] = fmaxf(v1h + b1, 0.f);
    }
}

// ---------- shared tf32-mma input-projection phase ----------
// A_s: 64 rows x 68 pitch (tf32 bits). W_s: 64 k x 264 pitch, column-permuted so
// out col index == hcol*4+gate (matches g_pre float layout). bb_s: 256 permuted biases.
// Block tile: 64 rows x 256 cols; warp tile 32x64.
__device__ __forceinline__ void xproj_mma(const uint32_t* __restrict__ A_s,
                                          const uint32_t* __restrict__ W_s,
                                          const float* __restrict__ bb_s,
                                          int nb, int t){
    int lane = t & 31, w = t >> 5;
    int g = lane >> 2, tq = lane & 3;
    int mw = (w >> 2) * 32;
    int nw = (w & 3) * 64;
    float acc[2][8][4];
    #pragma unroll
    for (int mt = 0; mt < 2; ++mt)
        #pragma unroll
        for (int j = 0; j < 8; ++j)
            #pragma unroll
            for (int q = 0; q < 4; ++q) acc[mt][j][q] = 0.f;

    #pragma unroll
    for (int ks = 0; ks < 8; ++ks){
        int C = ks * 8;
        uint32_t a[2][4];
        #pragma unroll
        for (int mt = 0; mt < 2; ++mt){
            int R = mw + mt * 16;
            a[mt][0] = A_s[(R + g) * 68 + C + tq];
            a[mt][1] = A_s[(R + g + 8) * 68 + C + tq];
            a[mt][2] = A_s[(R + g) * 68 + C + tq + 4];
            a[mt][3] = A_s[(R + g + 8) * 68 + C + tq + 4];
        }
        uint32_t b[8][2];
        #pragma unroll
        for (int j = 0; j < 8; ++j){
            b[j][0] = W_s[(C + tq) * 264 + nw + 8 * j + g];
            b[j][1] = W_s[(C + tq + 4) * 264 + nw + 8 * j + g];
        }
        #pragma unroll
        for (int mt = 0; mt < 2; ++mt)
            #pragma unroll
            for (int j = 0; j < 8; ++j) mma_tf32(acc[mt][j], a[mt], b[j]);
    }
    #pragma unroll
    for (int mt = 0; mt < 2; ++mt){
        int r0 = nb + mw + mt * 16 + g;
        #pragma unroll
        for (int j = 0; j < 8; ++j){
            int col = nw + 8 * j + 2 * tq;
            float b0 = bb_s[col], b1 = bb_s[col + 1];
            *(float2*)&g_pre[r0 * 256 + col] =
                make_float2(acc[mt][j][0] + b0, acc[mt][j][1] + b1);
            *(float2*)&g_pre[(r0 + 8) * 256 + col] =
                make_float2(acc[mt][j][2] + b0, acc[mt][j][3] + b1);
        }
    }
}

// ---------- fused GCN layer 1 (FFMA2) + LSTM-0 input projection (tf32 mma) ----------
// floats: A1_s 64*66, W1_s 64*64, b1_s 64 | uints: A2_s 64*68, Wi_s 64*264 | bb_s 256
#define GX_F1   (64 * 66)
#define GX_F2   (GX_F1 + 64 * 64)
#define GX_F3   (GX_F2 + 64)
#define GX_U1   (GX_F3 + 64 * 68)
#define GX_U2   (GX_U1 + 64 * 264)
#define GX_TOT  (GX_U2 + 256)
#define GX_SMEM (GX_TOT * 4)

__global__ __launch_bounds__(256)
void k_gcn1x(const float* __restrict__ W1, const float* __restrict__ b1,
             const float* __restrict__ wih, const float* __restrict__ bih,
             const float* __restrict__ bhh){
    extern __shared__ __align__(16) float sm[];
    float*    A1_s = sm;
    float*    W1_s = sm + GX_F1;
    float*    b1_s = sm + GX_F2;
    uint32_t* A2_s = (uint32_t*)(sm + GX_F3);
    uint32_t* Wi_s = (uint32_t*)(sm + GX_U1);
    float*    bb_s = sm + GX_U2;
    int t  = threadIdx.x;
    int nb = blockIdx.x * 64;
    int jj = t & 31, wg = t >> 5;

    // stage: W1, b1, agg1 tile, Wih (permuted+tf32), permuted bias
    for (int idx = t; idx < 4096; idx += 256) W1_s[idx] = W1[idx];
    if (t < 64) b1_s[t] = b1[t];
    for (int idx = t; idx < 64 * 64; idx += 256){
        int n = idx >> 6, k = idx & 63;
        A1_s[k * 66 + n] = g_agg1[(nb + n) * 64 + k];
    }
    for (int idx = t; idx < 64 * 256; idx += 256){
        int r = idx >> 6, k = idx & 63;
        int gate = r >> 6, hcol = r & 63;
        Wi_s[k * 264 + hcol * 4 + gate] = tf32cvt(wih[r * 64 + k]);
    }
    {
        int hcol = t >> 2, gate = t & 3;
        bb_s[t] = bih[gate * 64 + hcol] + bhh[gate * 64 + hcol];
    }
    __syncthreads();

    // GEMM1 (FFMA2): h1 tile 64x64 -> A2_s (tf32, [row][k] pitch 68)
    {
        ull acc[4][2];
        #pragma unroll
        for (int p = 0; p < 4; ++p){ acc[p][0] = 0ull; acc[p][1] = 0ull; }
        #pragma unroll 8
        for (int k = 0; k < 64; ++k){
            float w0 = W1_s[k * 64 + jj], w1 = W1_s[k * 64 + jj + 32];
            ull W0 = pack2(w0, w0), W1v = pack2(w1, w1);
            const float* Ar = &A1_s[k * 66 + wg * 8];
            #pragma unroll
            for (int p = 0; p < 4; ++p){
                ull a = *(const ull*)(Ar + 2 * p);
                acc[p][0] = ffma2(a, W0, acc[p][0]);
                acc[p][1] = ffma2(a, W1v, acc[p][1]);
            }
        }
        float bb0 = b1_s[jj], bb1 = b1_s[jj + 32];
        #pragma unroll
        for (int p = 0; p < 4; ++p){
            float v0l, v0h, v1l, v1h;
            unpack2(acc[p][0], v0l, v0h);
            unpack2(acc[p][1], v1l, v1h);
            int r = wg * 8 + 2 * p;
            A2_s[r * 68 + jj]            = tf32cvt(fmaxf(v0l + bb0, 0.f));
            A2_s[(r + 1) * 68 + jj]      = tf32cvt(fmaxf(v0h + bb0, 0.f));
            A2_s[r * 68 + jj + 32]       = tf32cvt(fmaxf(v1l + bb1, 0.f));
            A2_s[(r + 1) * 68 + jj + 32] = tf32cvt(fmaxf(v1h + bb1, 0.f));
        }
    }
    __syncthreads();

    xproj_mma(A2_s, Wi_s, bb_s, nb, t);
}

// ---------- LSTM-1 input projection (tf32 mma): g_pre = g_hs0 @ Wih1^T + bias ----------
#define XP_U1   (64 * 68)
#define XP_U2   (XP_U1 + 64 * 264)
#define XP_TOT  (XP_U2 + 256)
#define XP_SMEM (XP_TOT * 4)

__global__ __launch_bounds__(256)
void k_xproj2(const float* __restrict__ wih, const float* __restrict__ bih,
              const float* __restrict__ bhh){
    extern __shared__ __align__(16) float sm[];
    uint32_t* A_s  = (uint32_t*)sm;
    uint32_t* Wi_s = (uint32_t*)sm + XP_U1;
    float*    bb_s = sm + XP_U2;
    int t  = threadIdx.x;
    int nb = blockIdx.x * 64;

    for (int idx = t; idx < 64 * 256; idx += 256){
        int r = idx >> 6, k = idx & 63;
        int gate = r >> 6, hcol = r & 63;
        Wi_s[k * 264 + hcol * 4 + gate] = tf32cvt(wih[r * 64 + k]);
    }
    {
        int hcol = t >> 2, gate = t & 3;
        bb_s[t] = bih[gate * 64 + hcol] + bhh[gate * 64 + hcol];
    }
    for (int idx = t; idx < 64 * 64; idx += 256){
        int n = idx >> 6, k = idx & 63;
        A_s[n * 68 + k] = tf32cvt(g_hs0[(nb + n) * 64 + k]);
    }
    __syncthreads();

    xproj_mma(A_s, Wi_s, bb_s, nb, t);
}

// ---------- persistent per-layer LSTM: 125 blocks x 80 nodes, 12 steps ----------
// layer 1 additionally computes the final FC in its epilogue.
#define LSTM_SMEM ((256 * 65 + 64 * 82 + 64 * 82) * 4)

__global__ __launch_bounds__(256, 1)
void k_lstm_layer(int layer, const float* __restrict__ whh,
                  const float* __restrict__ fcw, const float* __restrict__ fcb,
                  float* __restrict__ out){
    extern __shared__ float smem[];
    float* W_s = smem;                 // [c 0..255][kk 0..63], pitch 65
    float* h_s = smem + 256 * 65;      // [hcol 0..63][n 0..79], pitch 82
    float* c_s = h_s + 64 * 82;

    int t  = threadIdx.x;
    int jj = t & 31, wg = t >> 5;
    int nb = blockIdx.x * 80;

    for (int idx = t; idx < 256 * 64; idx += 256){
        int k = idx & 63, c = idx >> 6;
        W_s[c * 65 + k] = whh[idx];
    }
    for (int idx = t; idx < 64 * 82; idx += 256){
        h_s[idx] = 0.f;
        c_s[idx] = 0.f;
    }
    __syncthreads();

    for (int st = 0; st < TT; ++st){
        ull acc[8][5];
        #pragma unroll
        for (int g = 0; g < 8; ++g)
            #pragma unroll
            for (int p = 0; p < 5; ++p) acc[g][p] = 0ull;

        #pragma unroll 4
        for (int kk = 0; kk < 64; ++kk){
            const float* Ar = h_s + kk * 82 + wg * 10;
            ull a0 = *(const ull*)(Ar + 0);
            ull a1 = *(const ull*)(Ar + 2);
            ull a2 = *(const ull*)(Ar + 4);
            ull a3 = *(const ull*)(Ar + 6);
            ull a4 = *(const ull*)(Ar + 8);
            #pragma unroll
            for (int g = 0; g < 8; ++g){
                float w = W_s[(jj + 32 * g) * 65 + kk];
                ull W2 = pack2(w, w);
                acc[g][0] = ffma2(a0, W2, acc[g][0]);
                acc[g][1] = ffma2(a1, W2, acc[g][1]);
                acc[g][2] = ffma2(a2, W2, acc[g][2]);
                acc[g][3] = ffma2(a3, W2, acc[g][3]);
                acc[g][4] = ffma2(a4, W2, acc[g][4]);
            }
        }
        __syncthreads();

        #pragma unroll
        for (int p = 0; p < 5; ++p){
            #pragma unroll
            for (int hs2 = 0; hs2 < 2; ++hs2){
                int hcol = jj + 32 * hs2;
                float i0, i1, f0, f1, g0, g1, o0, o1;
                unpack2(acc[0 + hs2][p], i0, i1);
                unpack2(acc[2 + hs2][p], f0, f1);
                unpack2(acc[4 + hs2][p], g0, g1);
                unpack2(acc[6 + hs2][p], o0, o1);
                #pragma unroll
                for (int half = 0; half < 2; ++half){
                    int nloc = wg * 10 + 2 * p + half;
                    int node = nb + nloc;
                    float4 pv = ((const float4*)g_pre)[(node * TT + st) * 64 + hcol];
                    float iv = (half ? i1 : i0) + pv.x;
                    float fv = (half ? f1 : f0) + pv.y;
                    float gv = (half ? g1 : g0) + pv.z;
                    float ov = (half ? o1 : o0) + pv.w;
                    float cold = c_s[hcol * 82 + nloc];
                    float cn = fsig(fv) * cold + fsig(iv) * tanha(gv);
                    float hn = fsig(ov) * tanha(cn);
                    c_s[hcol * 82 + nloc] = cn;
                    h_s[hcol * 82 + nloc] = hn;
                    if (layer == 0)
                        g_hs0[(node * TT + st) * 64 + hcol] = hn;
                }
            }
        }
        __syncthreads();
    }

    if (layer == 1){
        // fused FC on final h (already in smem); reuse W_s as scratch for fc_w^T
        for (int idx = t; idx < 1024; idx += 256){
            int k = idx >> 4, o = idx & 15;
            W_s[k * 16 + o] = fcw[o * 64 + k];
        }
        __syncthreads();
        #pragma unroll
        for (int q = 0; q < 5; ++q){
            int oi = t + 256 * q;              // 0..1279 = 80 nodes x 16 outs
            int nloc = oi >> 4, o = oi & 15;
            float acc = fcb[o];
            #pragma unroll 8
            for (int k = 0; k < 64; ++k)
                acc += h_s[k * 82 + nloc] * W_s[k * 16 + o];
            out[(nb + nloc) * 16 + o] = acc;
        }
    }
}

extern "C" void kernel_launch(void* const* d_in, const int* in_sizes, int n_in,
                              void* d_out, int out_size){
    const float* x    = (const float*)d_in[0];
    const void*  ei   =               d_in[1];
    const float* gw0  = (const float*)d_in[2];
    const float* gb0  = (const float*)d_in[3];
    const float* gw1  = (const float*)d_in[4];
    const float* gb1  = (const float*)d_in[5];
    const float* wih0 = (const float*)d_in[6];
    const float* whh0 = (const float*)d_in[7];
    const float* bih0 = (const float*)d_in[8];
    const float* bhh0 = (const float*)d_in[9];
    const float* wih1 = (const float*)d_in[10];
    const float* whh1 = (const float*)d_in[11];
    const float* bih1 = (const float*)d_in[12];
    const float* bhh1 = (const float*)d_in[13];
    const float* fcw  = (const float*)d_in[14];
    const float* fcb  = (const float*)d_in[15];
    float* out = (float*)d_out;

    cudaFuncSetAttribute(k_lstm_layer, cudaFuncAttributeMaxDynamicSharedMemorySize, LSTM_SMEM);
    cudaFuncSetAttribute(k_gcn1x,      cudaFuncAttributeMaxDynamicSharedMemorySize, GX_SMEM);
    cudaFuncSetAttribute(k_xproj2,     cudaFuncAttributeMaxDynamicSharedMemorySize, XP_SMEM);

    // CSR build
    k_init <<<40, 256>>>((const int*)ei);
    k_count<<<(NE + 255) / 256, 256>>>(ei);
    k_scan1<<<79, 128>>>();
    k_scan3<<<79, 128>>>();
    k_fill <<<(NE + 255) / 256, 256>>>(ei);

    // GCN layer 0
    k_agg_x<<<NN, 128>>>(x);
    k_gcn_gemm0<<<1250, 256>>>(gw0, gb0);
    // GCN layer 1 fused with LSTM-0 input projection (tf32 mma)
    k_agg_h<<<NN, 256>>>();
    k_gcn1x<<<1875, 256, GX_SMEM>>>(gw1, gb1, wih0, bih0, bhh0);

    // LSTM layer 0
    k_lstm_layer<<<125, 256, LSTM_SMEM>>>(0, whh0, fcw, fcb, out);

    // LSTM layer 1 (input projection via tf32 mma, FC fused into epilogue)
    k_xproj2<<<1875, 256, XP_SMEM>>>(wih1, bih1, bhh1);
    k_lstm_layer<<<125, 256, LSTM_SMEM>>>(1, whh1, fcw, fcb, out);
}

// round 12
// speedup vs baseline: 1.3923x; 1.3923x over previous
#include <cuda_runtime.h>
#include <math.h>

#define NN  10000
#define NE  160000
#define TT  12
#define FIN 32
#define HH  64

typedef unsigned long long ull;

// ---------- packed f32x2 helpers ----------
__device__ __forceinline__ ull ffma2(ull a, ull b, ull c){
    ull d; asm("fma.rn.f32x2 %0, %1, %2, %3;" : "=l"(d) : "l"(a), "l"(b), "l"(c)); return d;
}
__device__ __forceinline__ ull pack2(float lo, float hi){
    ull r; asm("mov.b64 %0, {%1, %2};" : "=l"(r) : "f"(lo), "f"(hi)); return r;
}
__device__ __forceinline__ void unpack2(ull v, float& lo, float& hi){
    asm("mov.b64 {%0, %1}, %2;" : "=f"(lo), "=f"(hi) : "l"(v));
}
__device__ __forceinline__ float tanha(float x){
    float y; asm("tanh.approx.f32 %0, %1;" : "=f"(y) : "f"(x)); return y;
}
__device__ __forceinline__ float fsig(float x){ return 0.5f * tanha(0.5f * x) + 0.5f; }

__device__ int   g_is64;
__device__ int   g_cnt[NN];
__device__ int   g_off[NN];
__device__ int   g_cur[NN];
__device__ int   g_src[NE];
__device__ int   g_bsum[80];
__device__ float g_dis[NN];
__device__ float g_h0  [NN * TT * HH];
__device__ float g_agg1[NN * TT * HH];
__device__ float g_hs0 [NN * TT * HH];
__device__ float g_pre [NN * TT * 256];     // float4 layout: [row][hcol]{i,f,g,o}

// ---------- CSR build ----------
__global__ void k_init(const int* __restrict__ w){
    int i = blockIdx.x * blockDim.x + threadIdx.x;
    if (i < NN) g_cnt[i] = 0;
    if (blockIdx.x == 0 && threadIdx.x == 0){
        int any = 0;
        #pragma unroll
        for (int j = 1; j < 129; j += 2) any |= w[j];
        g_is64 = (any == 0) ? 1 : 0;
    }
}

__global__ void k_count(const void* __restrict__ ei){
    int e = blockIdx.x * blockDim.x + threadIdx.x;
    if (e >= NE) return;
    int c = g_is64 ? (int)((const long long*)ei)[NE + e]
                   : ((const int*)ei)[NE + e];
    atomicAdd(&g_cnt[c], 1);
}

__global__ void k_scan1(){
    int b = blockIdx.x, t = threadIdx.x;
    int i = b * 128 + t;
    int v = (i < NN) ? g_cnt[i] : 0;
    int lane = t & 31, w = t >> 5;
    int s = v;
    #pragma unroll
    for (int d = 16; d > 0; d >>= 1) s += __shfl_down_sync(0xffffffffu, s, d);
    __shared__ int ws[4];
    if (lane == 0) ws[w] = s;
    __syncthreads();
    if (t == 0) g_bsum[b] = ws[0] + ws[1] + ws[2] + ws[3];
}

__global__ void k_scan3(){
    int b = blockIdx.x, t = threadIdx.x;
    __shared__ int sbase;
    __shared__ int ws[4];
    if (t < 32){
        int s = 0;
        for (int i = t; i < b; i += 32) s += g_bsum[i];
        #pragma unroll
        for (int d = 16; d > 0; d >>= 1) s += __shfl_down_sync(0xffffffffu, s, d);
        if (t == 0) sbase = s;
    }
    int i = b * 128 + t;
    int v = (i < NN) ? g_cnt[i] : 0;
    int lane = t & 31, w = t >> 5;
    int incl = v;
    #pragma unroll
    for (int d = 1; d < 32; d <<= 1){
        int o = __shfl_up_sync(0xffffffffu, incl, d);
        if (lane >= d) incl += o;
    }
    if (lane == 31) ws[w] = incl;
    __syncthreads();
    int base = sbase;
    for (int k = 0; k < w; ++k) base += ws[k];
    if (i < NN){
        g_off[i] = base + incl - v;
        g_cur[i] = 0;
        g_dis[i] = rsqrtf((float)(v + 1));
    }
}

__global__ void k_fill(const void* __restrict__ ei){
    int e = blockIdx.x * blockDim.x + threadIdx.x;
    if (e >= NE) return;
    int r, c;
    if (g_is64){
        r = (int)((const long long*)ei)[e];
        c = (int)((const long long*)ei)[NE + e];
    } else {
        r = ((const int*)ei)[e];
        c = ((const int*)ei)[NE + e];
    }
    int p = atomicAdd(&g_cur[c], 1);
    g_src[g_off[c] + p] = r;
}

// ---------- fused: aggregate raw x + GCN layer-0 GEMM + relu -> g_h0 ----------
// one block per target node c; gather (T,F)=(12,32) tile, then tile @ W0(32x64)+b0
__global__ __launch_bounds__(128)
void k_aggx_gcn0(const float* __restrict__ x, const float* __restrict__ W,
                 const float* __restrict__ bvec){
    __shared__ float s_ag[12 * 33];
    __shared__ float W_s[32 * 64];
    __shared__ float b_s[64];
    int c   = blockIdx.x;
    int off = g_off[c], len = g_cnt[c];
    float dc = g_dis[c];
    int t = threadIdx.x;

    // stage W/b while gathering
    for (int idx = t; idx < 2048; idx += 128) W_s[idx] = W[idx];
    if (t < 64) b_s[t] = bvec[t];

    int p0 = t, p1 = t + 128, p2 = t + 256;
    int b0 = (p0 >> 5) * (NN * FIN) + (p0 & 31);
    int b1 = (p1 >> 5) * (NN * FIN) + (p1 & 31);
    int b2 = (p2 >> 5) * (NN * FIN) + (p2 & 31);
    int cb = c * FIN;
    float a0 = dc * x[b0 + cb];
    float a1 = dc * x[b1 + cb];
    float a2 = dc * x[b2 + cb];
    for (int e = 0; e < len; ++e){
        int r = g_src[off + e];
        float dr = g_dis[r];
        int rb = r * FIN;
        a0 += dr * x[b0 + rb];
        a1 += dr * x[b1 + rb];
        a2 += dr * x[b2 + rb];
    }
    s_ag[(p0 >> 5) * 33 + (p0 & 31)] = dc * a0;
    s_ag[(p1 >> 5) * 33 + (p1 & 31)] = dc * a1;
    s_ag[(p2 >> 5) * 33 + (p2 & 31)] = dc * a2;
    __syncthreads();

    // GEMM: thread t -> col = t&63, T = (t>>6) + 2q (q<6)
    int col = t & 63;
    int Tb  = t >> 6;
    float acc[6];
    #pragma unroll
    for (int q = 0; q < 6; ++q) acc[q] = b_s[col];
    #pragma unroll 8
    for (int f = 0; f < 32; ++f){
        float w = W_s[f * 64 + col];
        #pragma unroll
        for (int q = 0; q < 6; ++q)
            acc[q] += s_ag[(Tb + 2 * q) * 33 + f] * w;
    }
    #pragma unroll
    for (int q = 0; q < 6; ++q)
        g_h0[(c * TT + Tb + 2 * q) * 64 + col] = fmaxf(acc[q], 0.f);
}

// ---------- aggregate h0 (N,T,64) -> (N,T,64) ----------
__global__ void k_agg_h(){
    int c   = blockIdx.x;
    int off = g_off[c], len = g_cnt[c];
    float dc = g_dis[c];
    int t = threadIdx.x;
    int cb = c * 768;
    float a0 = dc * g_h0[cb + t];
    float a1 = dc * g_h0[cb + t + 256];
    float a2 = dc * g_h0[cb + t + 512];
    for (int e = 0; e < len; ++e){
        int r = g_src[off + e];
        float dr = g_dis[r];
        int rb = r * 768;
        a0 += dr * g_h0[rb + t];
        a1 += dr * g_h0[rb + t + 256];
        a2 += dr * g_h0[rb + t + 512];
    }
    g_agg1[cb + t]       = dc * a0;
    g_agg1[cb + t + 256] = dc * a1;
    g_agg1[cb + t + 512] = dc * a2;
}

// ---------- fused GCN layer 1 (FFMA2) + LSTM-0 input projection ----------
// h1 = relu(g_agg1 @ W1 + b1) kept in smem; g_pre = h1 @ Wih0^T + (bih0+bhh0)
#define GX_SMEM (25152 * 4)
__global__ __launch_bounds__(256)
void k_gcn1x(const float* __restrict__ W1, const float* __restrict__ b1,
             const float* __restrict__ wih, const float* __restrict__ bih,
             const float* __restrict__ bhh){
    extern __shared__ float sm[];
    float* A_s  = sm;             // 64 x 98  (agg1 tile, [k][n])
    float* W1_s = sm + 6272;      // 64 x 64
    float* b1_s = sm + 10368;     // 64
    float* A2_s = sm + 10432;     // 64 x 98  (h1 tile, [col][n])
    float* Wi_s = sm + 16704;     // 128 x 65
    float* bb_s = sm + 25024;     // 128
    int t  = threadIdx.x;
    int nb = blockIdx.x * 96;
    int jj = t & 31, pg = t >> 5;

    for (int idx = t; idx < 4096; idx += 256) W1_s[idx] = W1[idx];
    if (t < 64) b1_s[t] = b1[t];
    for (int idx = t; idx < 96 * 64; idx += 256){
        int n = idx >> 6, k = idx & 63;
        A_s[k * 98 + n] = g_agg1[(nb + n) * 64 + k];
    }
    __syncthreads();

    {   // GEMM1: 96 x 64
        ull acc[6][2];
        #pragma unroll
        for (int p = 0; p < 6; ++p){ acc[p][0] = 0ull; acc[p][1] = 0ull; }
        #pragma unroll 8
        for (int k = 0; k < 64; ++k){
            float w0 = W1_s[k * 64 + jj], w1 = W1_s[k * 64 + jj + 32];
            ull W0 = pack2(w0, w0), W1v = pack2(w1, w1);
            const float* Ar = &A_s[k * 98 + pg * 12];
            #pragma unroll
            for (int p = 0; p < 6; ++p){
                ull a = *(const ull*)(Ar + 2 * p);
                acc[p][0] = ffma2(a, W0, acc[p][0]);
                acc[p][1] = ffma2(a, W1v, acc[p][1]);
            }
        }
        float bb0 = b1_s[jj], bb1 = b1_s[jj + 32];
        #pragma unroll
        for (int p = 0; p < 6; ++p){
            float v0l, v0h, v1l, v1h;
            unpack2(acc[p][0], v0l, v0h);
            unpack2(acc[p][1], v1l, v1h);
            int n0 = pg * 12 + 2 * p;
            A2_s[jj * 98 + n0]            = fmaxf(v0l + bb0, 0.f);
            A2_s[jj * 98 + n0 + 1]        = fmaxf(v0h + bb0, 0.f);
            A2_s[(jj + 32) * 98 + n0]     = fmaxf(v1l + bb1, 0.f);
            A2_s[(jj + 32) * 98 + n0 + 1] = fmaxf(v1h + bb1, 0.f);
        }
    }
    __syncthreads();

    for (int half = 0; half < 2; ++half){
        for (int idx = t; idx < 128 * 64; idx += 256){
            int r = idx >> 6, k = idx & 63;
            int grow = (r >> 5) * 64 + half * 32 + (r & 31);
            Wi_s[r * 65 + k] = wih[grow * 64 + k];
        }
        if (t < 128){
            int grow = (t >> 5) * 64 + half * 32 + (t & 31);
            bb_s[t] = bih[grow] + bhh[grow];
        }
        __syncthreads();

        ull acc2[6][4];
        #pragma unroll
        for (int p = 0; p < 6; ++p)
            #pragma unroll
            for (int g = 0; g < 4; ++g) acc2[p][g] = 0ull;

        #pragma unroll 4
        for (int k = 0; k < 64; ++k){
            const float* Ar = &A2_s[k * 98 + pg * 12];
            ull a0 = *(const ull*)(Ar + 0);
            ull a1 = *(const ull*)(Ar + 2);
            ull a2 = *(const ull*)(Ar + 4);
            ull a3 = *(const ull*)(Ar + 6);
            ull a4 = *(const ull*)(Ar + 8);
            ull a5 = *(const ull*)(Ar + 10);
            #pragma unroll
            for (int g = 0; g < 4; ++g){
                float w = Wi_s[(g * 32 + jj) * 65 + k];
                ull W2 = pack2(w, w);
                acc2[0][g] = ffma2(a0, W2, acc2[0][g]);
                acc2[1][g] = ffma2(a1, W2, acc2[1][g]);
                acc2[2][g] = ffma2(a2, W2, acc2[2][g]);
                acc2[3][g] = ffma2(a3, W2, acc2[3][g]);
                acc2[4][g] = ffma2(a4, W2, acc2[4][g]);
                acc2[5][g] = ffma2(a5, W2, acc2[5][g]);
            }
        }
        float bi = bb_s[jj], bf = bb_s[32 + jj], bg = bb_s[64 + jj], bo = bb_s[96 + jj];
        int hcol = half * 32 + jj;
        #pragma unroll
        for (int p = 0; p < 6; ++p){
            float i0, i1, f0, f1, g0, g1, o0, o1;
            unpack2(acc2[p][0], i0, i1);
            unpack2(acc2[p][1], f0, f1);
            unpack2(acc2[p][2], g0, g1);
            unpack2(acc2[p][3], o0, o1);
            int row = nb + pg * 12 + 2 * p;
            ((float4*)g_pre)[row * 64 + hcol]       = make_float4(i0 + bi, f0 + bf, g0 + bg, o0 + bo);
            ((float4*)g_pre)[(row + 1) * 64 + hcol] = make_float4(i1 + bi, f1 + bf, g1 + bg, o1 + bo);
        }
        __syncthreads();
    }
}

// ---------- LSTM-1 input projection: g_pre = g_hs0 @ Wih1^T + bias ----------
#define XP_SMEM (14720 * 4)
__global__ __launch_bounds__(256)
void k_xproj2(const float* __restrict__ wih, const float* __restrict__ bih,
              const float* __restrict__ bhh){
    extern __shared__ float sm[];
    float* A_s  = sm;            // 64 x 98
    float* Wi_s = sm + 6272;     // 128 x 65
    float* bb_s = sm + 14592;    // 128
    int t  = threadIdx.x;
    int nb = blockIdx.x * 96;
    int cb = blockIdx.y * 32;
    int jj = t & 31, pg = t >> 5;

    for (int idx = t; idx < 128 * 64; idx += 256){
        int r = idx >> 6, k = idx & 63;
        int grow = (r >> 5) * 64 + cb + (r & 31);
        Wi_s[r * 65 + k] = wih[grow * 64 + k];
    }
    if (t < 128){
        int grow = (t >> 5) * 64 + cb + (t & 31);
        bb_s[t] = bih[grow] + bhh[grow];
    }
    for (int idx = t; idx < 96 * 64; idx += 256){
        int n = idx >> 6, k = idx & 63;
        A_s[k * 98 + n] = g_hs0[(nb + n) * 64 + k];
    }
    __syncthreads();

    ull acc2[6][4];
    #pragma unroll
    for (int p = 0; p < 6; ++p)
        #pragma unroll
        for (int g = 0; g < 4; ++g) acc2[p][g] = 0ull;

    #pragma unroll 4
    for (int k = 0; k < 64; ++k){
        const float* Ar = &A_s[k * 98 + pg * 12];
        ull a0 = *(const ull*)(Ar + 0);
        ull a1 = *(const ull*)(Ar + 2);
        ull a2 = *(const ull*)(Ar + 4);
        ull a3 = *(const ull*)(Ar + 6);
        ull a4 = *(const ull*)(Ar + 8);
        ull a5 = *(const ull*)(Ar + 10);
        #pragma unroll
        for (int g = 0; g < 4; ++g){
            float w = Wi_s[(g * 32 + jj) * 65 + k];
            ull W2 = pack2(w, w);
            acc2[0][g] = ffma2(a0, W2, acc2[0][g]);
            acc2[1][g] = ffma2(a1, W2, acc2[1][g]);
            acc2[2][g] = ffma2(a2, W2, acc2[2][g]);
            acc2[3][g] = ffma2(a3, W2, acc2[3][g]);
            acc2[4][g] = ffma2(a4, W2, acc2[4][g]);
            acc2[5][g] = ffma2(a5, W2, acc2[5][g]);
        }
    }
    float bi = bb_s[jj], bf = bb_s[32 + jj], bg = bb_s[64 + jj], bo = bb_s[96 + jj];
    int hcol = cb + jj;
    #pragma unroll
    for (int p = 0; p < 6; ++p){
        float i0, i1, f0, f1, g0, g1, o0, o1;
        unpack2(acc2[p][0], i0, i1);
        unpack2(acc2[p][1], f0, f1);
        unpack2(acc2[p][2], g0, g1);
        unpack2(acc2[p][3], o0, o1);
        int row = nb + pg * 12 + 2 * p;
        ((float4*)g_pre)[row * 64 + hcol]       = make_float4(i0 + bi, f0 + bf, g0 + bg, o0 + bo);
        ((float4*)g_pre)[(row + 1) * 64 + hcol] = make_float4(i1 + bi, f1 + bf, g1 + bg, o1 + bo);
    }
}

// ---------- persistent per-layer LSTM: 125 blocks x 80 nodes, 12 steps ----------
// layer 1 additionally computes the final FC in its epilogue.
// g_pre for step st is prefetched into registers BEFORE the GEMM so the
// scattered LDG.128 latency drains under the ~10k-cycle FFMA2 loop.
#define LSTM_SMEM ((256 * 65 + 64 * 82 + 64 * 82) * 4)

__global__ __launch_bounds__(256, 1)
void k_lstm_layer(int layer, const float* __restrict__ whh,
                  const float* __restrict__ fcw, const float* __restrict__ fcb,
                  float* __restrict__ out){
    extern __shared__ float smem[];
    float* W_s = smem;                 // [c 0..255][kk 0..63], pitch 65
    float* h_s = smem + 256 * 65;      // [hcol 0..63][n 0..79], pitch 82
    float* c_s = h_s + 64 * 82;

    int t  = threadIdx.x;
    int jj = t & 31, wg = t >> 5;
    int nb = blockIdx.x * 80;

    for (int idx = t; idx < 256 * 64; idx += 256){
        int k = idx & 63, c = idx >> 6;
        W_s[c * 65 + k] = whh[idx];
    }
    for (int idx = t; idx < 64 * 82; idx += 256){
        h_s[idx] = 0.f;
        c_s[idx] = 0.f;
    }
    __syncthreads();

    for (int st = 0; st < TT; ++st){
        // prefetch this step's pre-activations (independent of h)
        float4 pv[5][2][2];
        #pragma unroll
        for (int p = 0; p < 5; ++p)
            #pragma unroll
            for (int hs2 = 0; hs2 < 2; ++hs2)
                #pragma unroll
                for (int half = 0; half < 2; ++half){
                    int nloc = wg * 10 + 2 * p + half;
                    int hcol = jj + 32 * hs2;
                    pv[p][hs2][half] =
                        ((const float4*)g_pre)[((nb + nloc) * TT + st) * 64 + hcol];
                }

        ull acc[8][5];
        #pragma unroll
        for (int g = 0; g < 8; ++g)
            #pragma unroll
            for (int p = 0; p < 5; ++p) acc[g][p] = 0ull;

        #pragma unroll 4
        for (int kk = 0; kk < 64; ++kk){
            const float* Ar = h_s + kk * 82 + wg * 10;
            ull a0 = *(const ull*)(Ar + 0);
            ull a1 = *(const ull*)(Ar + 2);
            ull a2 = *(const ull*)(Ar + 4);
            ull a3 = *(const ull*)(Ar + 6);
            ull a4 = *(const ull*)(Ar + 8);
            #pragma unroll
            for (int g = 0; g < 8; ++g){
                float w = W_s[(jj + 32 * g) * 65 + kk];
                ull W2 = pack2(w, w);
                acc[g][0] = ffma2(a0, W2, acc[g][0]);
                acc[g][1] = ffma2(a1, W2, acc[g][1]);
                acc[g][2] = ffma2(a2, W2, acc[g][2]);
                acc[g][3] = ffma2(a3, W2, acc[g][3]);
                acc[g][4] = ffma2(a4, W2, acc[g][4]);
            }
        }
        __syncthreads();

        #pragma unroll
        for (int p = 0; p < 5; ++p){
            #pragma unroll
            for (int hs2 = 0; hs2 < 2; ++hs2){
                int hcol = jj + 32 * hs2;
                float i0, i1, f0, f1, g0, g1, o0, o1;
                unpack2(acc[0 + hs2][p], i0, i1);
                unpack2(acc[2 + hs2][p], f0, f1);
                unpack2(acc[4 + hs2][p], g0, g1);
                unpack2(acc[6 + hs2][p], o0, o1);
                #pragma unroll
                for (int half = 0; half < 2; ++half){
                    int nloc = wg * 10 + 2 * p + half;
                    int node = nb + nloc;
                    float4 pvv = pv[p][hs2][half];
                    float iv = (half ? i1 : i0) + pvv.x;
                    float fv = (half ? f1 : f0) + pvv.y;
                    float gv = (half ? g1 : g0) + pvv.z;
                    float ov = (half ? o1 : o0) + pvv.w;
                    float cold = c_s[hcol * 82 + nloc];
                    float cn = fsig(fv) * cold + fsig(iv) * tanha(gv);
                    float hn = fsig(ov) * tanha(cn);
                    c_s[hcol * 82 + nloc] = cn;
                    h_s[hcol * 82 + nloc] = hn;
                    if (layer == 0)
                        g_hs0[(node * TT + st) * 64 + hcol] = hn;
                }
            }
        }
        __syncthreads();
    }

    if (layer == 1){
        // fused FC on final h (already in smem); reuse W_s for fc_w^T
        for (int idx = t; idx < 1024; idx += 256){
            int k = idx >> 4, o = idx & 15;
            W_s[k * 16 + o] = fcw[o * 64 + k];
        }
        __syncthreads();
        #pragma unroll
        for (int q = 0; q < 5; ++q){
            int oi = t + 256 * q;              // 80 nodes x 16 outs
            int nloc = oi >> 4, o = oi & 15;
            float acc = fcb[o];
            #pragma unroll 8
            for (int k = 0; k < 64; ++k)
                acc += h_s[k * 82 + nloc] * W_s[k * 16 + o];
            out[(nb + nloc) * 16 + o] = acc;
        }
    }
}

extern "C" void kernel_launch(void* const* d_in, const int* in_sizes, int n_in,
                              void* d_out, int out_size){
    const float* x    = (const float*)d_in[0];
    const void*  ei   =               d_in[1];
    const float* gw0  = (const float*)d_in[2];
    const float* gb0  = (const float*)d_in[3];
    const float* gw1  = (const float*)d_in[4];
    const float* gb1  = (const float*)d_in[5];
    const float* wih0 = (const float*)d_in[6];
    const float* whh0 = (const float*)d_in[7];
    const float* bih0 = (const float*)d_in[8];
    const float* bhh0 = (const float*)d_in[9];
    const float* wih1 = (const float*)d_in[10];
    const float* whh1 = (const float*)d_in[11];
    const float* bih1 = (const float*)d_in[12];
    const float* bhh1 = (const float*)d_in[13];
    const float* fcw  = (const float*)d_in[14];
    const float* fcb  = (const float*)d_in[15];
    float* out = (float*)d_out;

    cudaFuncSetAttribute(k_lstm_layer, cudaFuncAttributeMaxDynamicSharedMemorySize, LSTM_SMEM);
    cudaFuncSetAttribute(k_gcn1x,      cudaFuncAttributeMaxDynamicSharedMemorySize, GX_SMEM);
    cudaFuncSetAttribute(k_xproj2,     cudaFuncAttributeMaxDynamicSharedMemorySize, XP_SMEM);

    // CSR build
    k_init <<<40, 256>>>((const int*)ei);
    k_count<<<(NE + 255) / 256, 256>>>(ei);
    k_scan1<<<79, 128>>>();
    k_scan3<<<79, 128>>>();
    k_fill <<<(NE + 255) / 256, 256>>>(ei);

    // GCN layer 0 (aggregation + GEMM fused)
    k_aggx_gcn0<<<NN, 128>>>(x, gw0, gb0);
    // GCN layer 1 fused with LSTM-0 input projection
    k_agg_h<<<NN, 256>>>();
    k_gcn1x<<<1250, 256, GX_SMEM>>>(gw1, gb1, wih0, bih0, bhh0);

    // LSTM layer 0
    k_lstm_layer<<<125, 256, LSTM_SMEM>>>(0, whh0, fcw, fcb, out);

    // LSTM layer 1 (FC fused into epilogue)
    {
        dim3 gx(1250, 2);
        k_xproj2<<<gx, 256, XP_SMEM>>>(wih1, bih1, bhh1);
    }
    k_lstm_layer<<<125, 256, LSTM_SMEM>>>(1, whh1, fcw, fcb, out);
}